// round 14
// baseline (speedup 1.0000x reference)
#include <cuda_runtime.h>
#include <cuda_fp16.h>
#include <math.h>
#include <stdint.h>

// Fixed problem shapes
#define EE 400000
#define NN 50000
#define RR 6
#define HH 128
#define DD 256

// Flat pre-swizzled fp16 weights: 28 chunks x 8192 halves (16KB).
#define NCHUNK_TOTAL 28      // wup:4  W0:8  W1:8  W2:8   (K32 chunks)
#define CH_FL 8192
__device__ __half g_wflat[(size_t)NCHUNK_TOTAL * CH_FL];

// SMEM (halves): t strip 128 x 264 | 4 weight stages of 8192 | mbars
#define TSTR2 264
#define T_FL2 (128 * TSTR2)                       // 33792 halves
#define MBAR_OFF ((T_FL2 + 4 * CH_FL) * 2)        // 133120 bytes
#define SMEM_BYTES (MBAR_OFF + 32)                // 133152 -> 1 CTA/SM

// ------------------------------------------------------------------
__device__ __forceinline__ uint32_t smem_u32(const void* p) {
    uint32_t a;
    asm("{ .reg .u64 t; cvta.to.shared.u64 t, %1; cvt.u32.u64 %0, t; }"
        : "=r"(a) : "l"(p));
    return a;
}
__device__ __forceinline__ void ldsm4(uint32_t& r0, uint32_t& r1,
                                      uint32_t& r2, uint32_t& r3,
                                      uint32_t addr) {
    asm volatile("ldmatrix.sync.aligned.m8n8.x4.shared.b16 {%0,%1,%2,%3}, [%4];"
                 : "=r"(r0), "=r"(r1), "=r"(r2), "=r"(r3) : "r"(addr));
}
__device__ __forceinline__ void mma_f16(float* c, const uint32_t* a,
                                        const uint32_t* b) {
    asm volatile(
        "mma.sync.aligned.m16n8k16.row.col.f32.f16.f16.f32 "
        "{%0,%1,%2,%3}, {%4,%5,%6,%7}, {%8,%9}, {%0,%1,%2,%3};"
        : "+f"(c[0]), "+f"(c[1]), "+f"(c[2]), "+f"(c[3])
        : "r"(a[0]), "r"(a[1]), "r"(a[2]), "r"(a[3]), "r"(b[0]), "r"(b[1]));
}
__device__ __forceinline__ float silu(float v) {
    return __fdividef(v, 1.f + __expf(-v));
}
__device__ __forceinline__ void red_add_v4(float* addr, float a, float b,
                                           float c, float d) {
    asm volatile("red.global.add.v4.f32 [%0], {%1, %2, %3, %4};"
                 :: "l"(addr), "f"(a), "f"(b), "f"(c), "f"(d) : "memory");
}
__device__ __forceinline__ void issue_bulk(uint32_t mbar, uint32_t dst,
                                           const __half* src) {
    asm volatile("mbarrier.arrive.expect_tx.shared.b64 _, [%0], %1;"
                 :: "r"(mbar), "r"(16384u) : "memory");
    asm volatile(
        "cp.async.bulk.shared::cta.global.mbarrier::complete_tx::bytes "
        "[%0], [%1], %2, [%3];"
        :: "r"(dst), "l"(src), "r"(16384u), "r"(mbar) : "memory");
}
__device__ __forceinline__ void mbar_wait(uint32_t mbar, uint32_t parity) {
    asm volatile(
        "{\n\t.reg .pred P;\n"
        "WAIT_%=:\n\t"
        "mbarrier.try_wait.parity.acquire.cta.shared::cta.b64 P, [%0], %1, 0x989680;\n\t"
        "@P bra.uni DONE_%=;\n\t"
        "bra.uni WAIT_%=;\n"
        "DONE_%=:\n\t}"
        :: "r"(mbar), "r"(parity) : "memory");
}

// ------------------------------------------------------------------
__global__ void zero_kernel(float4* p, int n4) {
    int i = blockIdx.x * blockDim.x + threadIdx.x;
    if (i < n4) p[i] = make_float4(0.f, 0.f, 0.f, 0.f);
}

// Build flat pre-swizzled fp16 weight image.
__global__ void convert_weights(const float* __restrict__ wup,
                                const float* __restrict__ Ws,
                                __half* __restrict__ wflat) {
    int i = blockIdx.x * blockDim.x + threadIdx.x;
    if (i >= NCHUNK_TOTAL * CH_FL) return;
    int g = i >> 13;
    int r = i & (CH_FL - 1);
    int n = r >> 5;
    int rest = r & 31;
    int sp = rest >> 3, j = rest & 7;
    int slog = sp ^ ((n >> 1) & 3);
    int kl = slog * 8 + j;
    float v;
    if (g < 4) {
        v = wup[(g * 32 + kl) * DD + n];
    } else {
        int gg = g - 4;
        int l = gg >> 3, k0 = (gg & 7) * 32;
        v = Ws[(size_t)l * DD * DD + (size_t)(k0 + kl) * DD + n];
    }
    wflat[i] = __float2half(v);
}

// ------------------------------------------------------------------
// One fp16 layer over the resident 128-row strip; weights via bulk stream.
// Pair-chunk schedule: per iteration issue chunks g+2,g+3, wait+compute
// chunks g and g+1 (K=64), single CTA barrier.
template<int NCH, bool ACT, bool LAST>
__device__ __forceinline__ void gemm_layer(
    __half* smh, uint32_t sbt, int gbase, const __half* __restrict__ wflat,
    const float* __restrict__ bias, const float* __restrict__ wout,
    float* __restrict__ out1, size_t e0)
{
    const int tid = threadIdx.x;
    const int warp = tid >> 5, lane = tid & 31;
    const int wm = warp & 1, wn = warp >> 1;      // wm: M half, wn: N block
    const int g2 = lane >> 2, t = lane & 3;
    const uint32_t mbar0 = sbt + MBAR_OFF;

    const uint32_t a_base = sbt +
        (uint32_t)((wm * 64 + (lane & 15)) * TSTR2 + ((lane & 16) ? 8 : 0)) * 2;

    const int sb_ = (lane & 8) ? 1 : 0;
    uint32_t rowoff[2];
    int sw[2];
#pragma unroll
    for (int np = 0; np < 2; np++) {
        int row = wn * 32 + np * 16 + (lane & 7) + ((lane & 16) ? 8 : 0);
        rowoff[np] = (uint32_t)row * 64u;
        sw[np] = (row >> 1) & 3;
    }

    float acc[4][4][4];
#pragma unroll
    for (int i = 0; i < 4; i++)
#pragma unroll
        for (int j = 0; j < 4; j++)
#pragma unroll
            for (int q = 0; q < 4; q++) acc[i][j][q] = 0.f;

#pragma unroll 1
    for (int p = 0; p < NCH / 2; p++) {
        const int g = gbase + 2 * p;
        if (tid == 0) {
            if (g + 2 < NCHUNK_TOTAL)
                issue_bulk(mbar0 + ((g + 2) & 3) * 8,
                           sbt + (uint32_t)(T_FL2 + ((g + 2) & 3) * CH_FL) * 2,
                           wflat + (size_t)(g + 2) * CH_FL);
            if (g + 3 < NCHUNK_TOTAL)
                issue_bulk(mbar0 + ((g + 3) & 3) * 8,
                           sbt + (uint32_t)(T_FL2 + ((g + 3) & 3) * CH_FL) * 2,
                           wflat + (size_t)(g + 3) * CH_FL);
        }
#pragma unroll
        for (int hh = 0; hh < 2; hh++) {
            const int gg = g + hh;
            mbar_wait(mbar0 + (gg & 3) * 8, (uint32_t)((gg >> 2) & 1));
            const uint32_t stg = sbt + (uint32_t)(T_FL2 + (gg & 3) * CH_FL) * 2;
#pragma unroll
            for (int ks = 0; ks < 2; ks++) {
                uint32_t af[4][4], bf[4][2];
                const uint32_t ak = (uint32_t)((2 * p + hh) * 32 + ks * 16) * 2;
#pragma unroll
                for (int mf = 0; mf < 4; mf++)
                    ldsm4(af[mf][0], af[mf][1], af[mf][2], af[mf][3],
                          a_base + ak + (uint32_t)(mf * 16 * TSTR2) * 2);
#pragma unroll
                for (int np = 0; np < 2; np++) {
                    uint32_t d0, d1, d2, d3;
                    uint32_t addr = stg + rowoff[np] +
                                    (uint32_t)(((2 * ks + sb_) ^ sw[np]) << 4);
                    ldsm4(d0, d1, d2, d3, addr);
                    bf[2 * np][0] = d0;     bf[2 * np][1] = d1;
                    bf[2 * np + 1][0] = d2; bf[2 * np + 1][1] = d3;
                }
#pragma unroll
                for (int mf = 0; mf < 4; mf++)
#pragma unroll
                    for (int nf = 0; nf < 4; nf++)
                        mma_f16(acc[mf][nf], af[mf], bf[nf]);
            }
        }
        __syncthreads();   // readers of this pair done before stages reused
    }

    if (!LAST) {
#pragma unroll
        for (int mf = 0; mf < 4; mf++) {
#pragma unroll
            for (int nf = 0; nf < 4; nf++) {
                int r0 = wm * 64 + mf * 16 + g2;
                int cc = wn * 32 + nf * 8 + 2 * t;
                float v0 = acc[mf][nf][0], v1 = acc[mf][nf][1];
                float v2 = acc[mf][nf][2], v3 = acc[mf][nf][3];
                if (ACT) {
                    float b0 = __ldg(bias + cc), b1 = __ldg(bias + cc + 1);
                    v0 = silu(v0 + b0); v1 = silu(v1 + b1);
                    v2 = silu(v2 + b0); v3 = silu(v3 + b1);
                }
                *reinterpret_cast<__half2*>(smh + r0 * TSTR2 + cc) =
                    __floats2half2_rn(v0, v1);
                *reinterpret_cast<__half2*>(smh + (r0 + 8) * TSTR2 + cc) =
                    __floats2half2_rn(v2, v3);
            }
        }
        __syncthreads();
    } else {
        float s0[4], s1[4];
#pragma unroll
        for (int mf = 0; mf < 4; mf++) { s0[mf] = 0.f; s1[mf] = 0.f; }
#pragma unroll
        for (int mf = 0; mf < 4; mf++) {
#pragma unroll
            for (int nf = 0; nf < 4; nf++) {
                int cc = wn * 32 + nf * 8 + 2 * t;
                float b0 = __ldg(bias + cc), b1 = __ldg(bias + cc + 1);
                float w0 = __ldg(wout + cc), w1 = __ldg(wout + cc + 1);
                s0[mf] += silu(acc[mf][nf][0] + b0) * w0
                        + silu(acc[mf][nf][1] + b1) * w1;
                s1[mf] += silu(acc[mf][nf][2] + b0) * w0
                        + silu(acc[mf][nf][3] + b1) * w1;
            }
        }
#pragma unroll
        for (int mf = 0; mf < 4; mf++) {
            s0[mf] += __shfl_xor_sync(0xffffffffu, s0[mf], 1);
            s0[mf] += __shfl_xor_sync(0xffffffffu, s0[mf], 2);
            s1[mf] += __shfl_xor_sync(0xffffffffu, s1[mf], 1);
            s1[mf] += __shfl_xor_sync(0xffffffffu, s1[mf], 2);
        }
        float* red = reinterpret_cast<float*>(smh + T_FL2); // stage region free
        if (t == 0) {
#pragma unroll
            for (int mf = 0; mf < 4; mf++) {
                int rl = wm * 64 + mf * 16 + g2;
                red[rl * 8 + wn] = s0[mf];
                red[(rl + 8) * 8 + wn] = s1[mf];
            }
        }
        __syncthreads();
        if (tid < 128) {
            float s = 0.f;
#pragma unroll
            for (int j = 0; j < 8; j++) s += red[tid * 8 + j];
            out1[e0 + tid] = s;
        }
    }
}

// ------------------------------------------------------------------
// Fully fused, M=128 strip: h (+fp32 vector scatter) -> W_up -> W0+silu
// -> W1+silu -> W2 + silu.w_out -> out1.
__global__ __launch_bounds__(512, 1)
void tower_fused(const float* __restrict__ x,  const float* __restrict__ rbf,
                 const int*   __restrict__ idx, const float* __restrict__ w_rbf,
                 const __half* __restrict__ wflat,
                 const float* __restrict__ bs, const float* __restrict__ wout,
                 float* __restrict__ xspe, float* __restrict__ out1)
{
    extern __shared__ __half smh[];
    const uint32_t sbt = smem_u32(smh);
    const uint32_t mbar0 = sbt + MBAR_OFF;
    const int tid = threadIdx.x;
    const size_t e0 = (size_t)blockIdx.x * 128;

    if (tid == 0) {
#pragma unroll
        for (int s = 0; s < 4; s++)
            asm volatile("mbarrier.init.shared.b64 [%0], 1;"
                         :: "r"(mbar0 + s * 8) : "memory");
    }
    __syncthreads();
    if (tid == 0) {
        issue_bulk(mbar0 + 0, sbt + (uint32_t)(T_FL2 + 0 * CH_FL) * 2, wflat);
        issue_bulk(mbar0 + 8, sbt + (uint32_t)(T_FL2 + 1 * CH_FL) * 2,
                   wflat + CH_FL);
    }

    // h phase: row r = tid/4 (0..127), cols (tid%4)*32 .. +31
    {
        const int r = tid >> 2;
        const int cg = (tid & 3) << 5;
        const float* xb = x + (e0 + r) * HH;
        const float* rb = rbf + (e0 + r) * RR;
        float r0 = __ldg(rb + 0), r1 = __ldg(rb + 1), r2 = __ldg(rb + 2);
        float r3 = __ldg(rb + 3), r4 = __ldg(rb + 4), r5 = __ldg(rb + 5);
        const int node = __ldg(idx + e0 + r);
        __half* trow = smh + r * TSTR2;
        float* xd = xspe + (size_t)node * HH;
#pragma unroll
        for (int cc = 0; cc < 32; cc += 4) {
            int c = cg + cc;
            float4 xv = __ldg((const float4*)(xb + c));
            float4 w0 = __ldg((const float4*)(w_rbf + 0 * HH + c));
            float4 w1 = __ldg((const float4*)(w_rbf + 1 * HH + c));
            float4 w2 = __ldg((const float4*)(w_rbf + 2 * HH + c));
            float4 w3 = __ldg((const float4*)(w_rbf + 3 * HH + c));
            float4 w4 = __ldg((const float4*)(w_rbf + 4 * HH + c));
            float4 w5 = __ldg((const float4*)(w_rbf + 5 * HH + c));
            float4 h;
            h.x = (r0*w0.x + r1*w1.x + r2*w2.x + r3*w3.x + r4*w4.x + r5*w5.x) * xv.x;
            h.y = (r0*w0.y + r1*w1.y + r2*w2.y + r3*w3.y + r4*w4.y + r5*w5.y) * xv.y;
            h.z = (r0*w0.z + r1*w1.z + r2*w2.z + r3*w3.z + r4*w4.z + r5*w5.z) * xv.z;
            h.w = (r0*w0.w + r1*w1.w + r2*w2.w + r3*w3.w + r4*w4.w + r5*w5.w) * xv.w;
            *reinterpret_cast<__half2*>(trow + c)     = __floats2half2_rn(h.x, h.y);
            *reinterpret_cast<__half2*>(trow + c + 2) = __floats2half2_rn(h.z, h.w);
            red_add_v4(xd + c, h.x, h.y, h.z, h.w);
        }
    }
    __syncthreads();

    // 4-layer tower; flat stream chunk bases: wup@0, W0@4, W1@12, W2@20
    gemm_layer<4,  false, false>(smh, sbt, 0,  wflat, nullptr, nullptr,
                                 nullptr, e0);
    gemm_layer<8,  true,  false>(smh, sbt, 4,  wflat, bs + 0 * DD, nullptr,
                                 nullptr, e0);
    gemm_layer<8,  true,  false>(smh, sbt, 12, wflat, bs + 1 * DD, nullptr,
                                 nullptr, e0);
    gemm_layer<8,  true,  true >(smh, sbt, 20, wflat, bs + 2 * DD, wout,
                                 out1, e0);
}

// ------------------------------------------------------------------
extern "C" void kernel_launch(void* const* d_in, const int* in_sizes, int n_in,
                              void* d_out, int out_size) {
    const float* x     = (const float*)d_in[0];
    const float* rbf   = (const float*)d_in[1];
    const int*   idx   = (const int*)  d_in[2];
    const float* w_rbf = (const float*)d_in[3];
    const float* w_up  = (const float*)d_in[4];
    const float* Ws    = (const float*)d_in[5];
    const float* bs    = (const float*)d_in[6];
    const float* w_out = (const float*)d_in[7];

    const int E = in_sizes[2];                    // 400000

    float* out_f = (float*)d_out;
    float* xspe  = out_f;                         // [N,128]
    float* out1  = out_f + (size_t)NN * HH;       // [E]

    __half* pwflat;
    cudaGetSymbolAddress((void**)&pwflat, g_wflat);

    cudaFuncSetAttribute(tower_fused,
                         cudaFuncAttributeMaxDynamicSharedMemorySize, SMEM_BYTES);

    // 0) build flat pre-swizzled fp16 weight image
    {
        int tot = NCHUNK_TOTAL * CH_FL;
        convert_weights<<<(tot + 255) / 256, 256>>>(w_up, Ws, pwflat);
    }
    // 1) zero x_spe (out1 fully written by the fused kernel)
    {
        int n4 = (NN * HH) / 4;
        zero_kernel<<<(n4 + 255) / 256, 256>>>((float4*)xspe, n4);
    }
    // 2) fully fused tower, M=128 strips
    {
        int grid = E / 128;                       // 3125
        tower_fused<<<grid, 512, SMEM_BYTES>>>(x, rbf, idx, w_rbf, pwflat,
                                               bs, w_out, xspe, out1);
    }
}

// round 15
// speedup vs baseline: 1.1431x; 1.1431x over previous
#include <cuda_runtime.h>
#include <cuda_fp16.h>
#include <math.h>
#include <stdint.h>

// Fixed problem shapes
#define EE 400000
#define NN 50000
#define RR 6
#define HH 128
#define DD 256

// Flat pre-swizzled fp16 weights: 28 chunks x 8192 halves (16KB).
// chunk g: rows n=0..255, k-cols k0..k0+31; within row, 8-half segment s
// stored at physical slot s ^ ((n>>1)&3).
#define NCHUNK_TOTAL 28      // wup:4  W0:8  W1:8  W2:8   (K32 chunks)
#define NPAIR_TOTAL 14
#define CH_FL 8192
__device__ __half g_wflat[(size_t)NCHUNK_TOTAL * CH_FL];

// SMEM (halves): t strip 64 x 264 | 4 weight stages of 8192 | 2 mbars
#define TSTR2 264
#define T_FL2 16896
#define MBAR_OFF ((T_FL2 + 4 * CH_FL) * 2)        // 99328 bytes
#define SMEM_BYTES (MBAR_OFF + 32)                // 99360 -> 2 CTAs/SM

// ------------------------------------------------------------------
__device__ __forceinline__ uint32_t smem_u32(const void* p) {
    uint32_t a;
    asm("{ .reg .u64 t; cvta.to.shared.u64 t, %1; cvt.u32.u64 %0, t; }"
        : "=r"(a) : "l"(p));
    return a;
}
__device__ __forceinline__ void ldsm4(uint32_t& r0, uint32_t& r1,
                                      uint32_t& r2, uint32_t& r3,
                                      uint32_t addr) {
    asm volatile("ldmatrix.sync.aligned.m8n8.x4.shared.b16 {%0,%1,%2,%3}, [%4];"
                 : "=r"(r0), "=r"(r1), "=r"(r2), "=r"(r3) : "r"(addr));
}
__device__ __forceinline__ void mma_f16(float* c, const uint32_t* a,
                                        const uint32_t* b) {
    asm volatile(
        "mma.sync.aligned.m16n8k16.row.col.f32.f16.f16.f32 "
        "{%0,%1,%2,%3}, {%4,%5,%6,%7}, {%8,%9}, {%0,%1,%2,%3};"
        : "+f"(c[0]), "+f"(c[1]), "+f"(c[2]), "+f"(c[3])
        : "r"(a[0]), "r"(a[1]), "r"(a[2]), "r"(a[3]), "r"(b[0]), "r"(b[1]));
}
__device__ __forceinline__ float silu(float v) {
    return __fdividef(v, 1.f + __expf(-v));
}
__device__ __forceinline__ void red_add_v4(float* addr, float a, float b,
                                           float c, float d) {
    asm volatile("red.global.add.v4.f32 [%0], {%1, %2, %3, %4};"
                 :: "l"(addr), "f"(a), "f"(b), "f"(c), "f"(d) : "memory");
}
__device__ __forceinline__ void bulk_cp(uint32_t mbar, uint32_t dst,
                                        const __half* src) {
    asm volatile(
        "cp.async.bulk.shared::cta.global.mbarrier::complete_tx::bytes "
        "[%0], [%1], %2, [%3];"
        :: "r"(dst), "l"(src), "r"(16384u), "r"(mbar) : "memory");
}
// pair p: chunks 2p,2p+1 -> stages 2(p&1), 2(p&1)+1; one mbar per parity
__device__ __forceinline__ void issue_pair(uint32_t sbt,
                                           const __half* __restrict__ wflat,
                                           int p) {
    const uint32_t mbar = sbt + MBAR_OFF + (uint32_t)(p & 1) * 8;
    asm volatile("mbarrier.arrive.expect_tx.shared.b64 _, [%0], %1;"
                 :: "r"(mbar), "r"(32768u) : "memory");
    const int st0 = 2 * (p & 1);
    bulk_cp(mbar, sbt + (uint32_t)(T_FL2 + st0 * CH_FL) * 2,
            wflat + (size_t)(2 * p) * CH_FL);
    bulk_cp(mbar, sbt + (uint32_t)(T_FL2 + (st0 + 1) * CH_FL) * 2,
            wflat + (size_t)(2 * p + 1) * CH_FL);
}
__device__ __forceinline__ void mbar_wait(uint32_t mbar, uint32_t parity) {
    asm volatile(
        "{\n\t.reg .pred P;\n"
        "WAIT_%=:\n\t"
        "mbarrier.try_wait.parity.acquire.cta.shared::cta.b64 P, [%0], %1, 0x989680;\n\t"
        "@P bra.uni DONE_%=;\n\t"
        "bra.uni WAIT_%=;\n"
        "DONE_%=:\n\t}"
        :: "r"(mbar), "r"(parity) : "memory");
}

// ------------------------------------------------------------------
__global__ void zero_kernel(float4* p, int n4) {
    int i = blockIdx.x * blockDim.x + threadIdx.x;
    if (i < n4) p[i] = make_float4(0.f, 0.f, 0.f, 0.f);
}

// Build flat pre-swizzled fp16 weight image.
__global__ void convert_weights(const float* __restrict__ wup,
                                const float* __restrict__ Ws,
                                __half* __restrict__ wflat) {
    int i = blockIdx.x * blockDim.x + threadIdx.x;
    if (i >= NCHUNK_TOTAL * CH_FL) return;
    int g = i >> 13;
    int r = i & (CH_FL - 1);
    int n = r >> 5;
    int rest = r & 31;
    int sp = rest >> 3, j = rest & 7;
    int slog = sp ^ ((n >> 1) & 3);       // logical k-segment
    int kl = slog * 8 + j;                // k within chunk
    float v;
    if (g < 4) {
        v = wup[(g * 32 + kl) * DD + n];
    } else {
        int gg = g - 4;
        int l = gg >> 3, k0 = (gg & 7) * 32;
        v = Ws[(size_t)l * DD * DD + (size_t)(k0 + kl) * DD + n];
    }
    wflat[i] = __float2half(v);
}

// ------------------------------------------------------------------
// One fp16 layer; weights arrive as chunk-PAIRS (one mbar wait per 64 K).
// pbase = first global pair of this layer; NP = pairs in this layer.
template<int NP, bool ACT, bool LAST>
__device__ __forceinline__ void gemm_layer(
    __half* smh, uint32_t sbt, int pbase, const __half* __restrict__ wflat,
    const float* __restrict__ bias, const float* __restrict__ wout,
    float* __restrict__ out1, size_t e0)
{
    const int tid = threadIdx.x;
    const int wn = tid >> 5, lane = tid & 31;
    const int g2 = lane >> 2, t = lane & 3;
    const uint32_t mbar0 = sbt + MBAR_OFF;

    const uint32_t a_base = sbt +
        (uint32_t)((lane & 15) * TSTR2 + ((lane & 16) ? 8 : 0)) * 2;

    const int sb_ = (lane & 8) ? 1 : 0;
    uint32_t rowoff[2];
    int sw[2];
#pragma unroll
    for (int np = 0; np < 2; np++) {
        int row = wn * 32 + np * 16 + (lane & 7) + ((lane & 16) ? 8 : 0);
        rowoff[np] = (uint32_t)row * 64u;
        sw[np] = (row >> 1) & 3;
    }

    float acc[4][4][4];
#pragma unroll
    for (int i = 0; i < 4; i++)
#pragma unroll
        for (int j = 0; j < 4; j++)
#pragma unroll
            for (int q = 0; q < 4; q++) acc[i][j][q] = 0.f;

#pragma unroll 1
    for (int lp = 0; lp < NP; lp++) {
        const int p = pbase + lp;
        // distance-1-pair prefetch (pairs 0,1 pre-issued in prologue)
        if (tid == 0 && p + 1 >= 2 && p + 1 < NPAIR_TOTAL)
            issue_pair(sbt, wflat, p + 1);
        mbar_wait(mbar0 + (uint32_t)(p & 1) * 8, (uint32_t)((p >> 1) & 1));

        const int st0 = 2 * (p & 1);
#pragma unroll
        for (int hh = 0; hh < 2; hh++) {
            const uint32_t stg = sbt + (uint32_t)(T_FL2 + (st0 + hh) * CH_FL) * 2;
#pragma unroll
            for (int ks = 0; ks < 2; ks++) {
                uint32_t af[4][4], bf[4][2];
                const uint32_t ak =
                    (uint32_t)((2 * lp + hh) * 32 + ks * 16) * 2;
#pragma unroll
                for (int mf = 0; mf < 4; mf++)
                    ldsm4(af[mf][0], af[mf][1], af[mf][2], af[mf][3],
                          a_base + ak + (uint32_t)(mf * 16 * TSTR2) * 2);
#pragma unroll
                for (int np = 0; np < 2; np++) {
                    uint32_t d0, d1, d2, d3;
                    uint32_t addr = stg + rowoff[np] +
                                    (uint32_t)(((2 * ks + sb_) ^ sw[np]) << 4);
                    ldsm4(d0, d1, d2, d3, addr);
                    bf[2 * np][0] = d0;     bf[2 * np][1] = d1;
                    bf[2 * np + 1][0] = d2; bf[2 * np + 1][1] = d3;
                }
#pragma unroll
                for (int mf = 0; mf < 4; mf++)
#pragma unroll
                    for (int nf = 0; nf < 4; nf++)
                        mma_f16(acc[mf][nf], af[mf], bf[nf]);
            }
        }
        __syncthreads();   // pair readers done before its stages are reused
    }

    if (!LAST) {
#pragma unroll
        for (int mf = 0; mf < 4; mf++) {
#pragma unroll
            for (int nf = 0; nf < 4; nf++) {
                int r0 = mf * 16 + g2;
                int cc = wn * 32 + nf * 8 + 2 * t;
                float v0 = acc[mf][nf][0], v1 = acc[mf][nf][1];
                float v2 = acc[mf][nf][2], v3 = acc[mf][nf][3];
                if (ACT) {
                    float b0 = __ldg(bias + cc), b1 = __ldg(bias + cc + 1);
                    v0 = silu(v0 + b0); v1 = silu(v1 + b1);
                    v2 = silu(v2 + b0); v3 = silu(v3 + b1);
                }
                *reinterpret_cast<__half2*>(smh + r0 * TSTR2 + cc) =
                    __floats2half2_rn(v0, v1);
                *reinterpret_cast<__half2*>(smh + (r0 + 8) * TSTR2 + cc) =
                    __floats2half2_rn(v2, v3);
            }
        }
        __syncthreads();
    } else {
        float s0[4], s1[4];
#pragma unroll
        for (int mf = 0; mf < 4; mf++) { s0[mf] = 0.f; s1[mf] = 0.f; }
#pragma unroll
        for (int mf = 0; mf < 4; mf++) {
#pragma unroll
            for (int nf = 0; nf < 4; nf++) {
                int cc = wn * 32 + nf * 8 + 2 * t;
                float b0 = __ldg(bias + cc), b1 = __ldg(bias + cc + 1);
                float w0 = __ldg(wout + cc), w1 = __ldg(wout + cc + 1);
                s0[mf] += silu(acc[mf][nf][0] + b0) * w0
                        + silu(acc[mf][nf][1] + b1) * w1;
                s1[mf] += silu(acc[mf][nf][2] + b0) * w0
                        + silu(acc[mf][nf][3] + b1) * w1;
            }
        }
#pragma unroll
        for (int mf = 0; mf < 4; mf++) {
            s0[mf] += __shfl_xor_sync(0xffffffffu, s0[mf], 1);
            s0[mf] += __shfl_xor_sync(0xffffffffu, s0[mf], 2);
            s1[mf] += __shfl_xor_sync(0xffffffffu, s1[mf], 1);
            s1[mf] += __shfl_xor_sync(0xffffffffu, s1[mf], 2);
        }
        float* red = reinterpret_cast<float*>(smh + T_FL2);
        if (t == 0) {
#pragma unroll
            for (int mf = 0; mf < 4; mf++) {
                red[(mf * 16 + g2) * 8 + wn] = s0[mf];
                red[(mf * 16 + 8 + g2) * 8 + wn] = s1[mf];
            }
        }
        __syncthreads();
        if (tid < 64) {
            float s = 0.f;
#pragma unroll
            for (int j = 0; j < 8; j++) s += red[tid * 8 + j];
            out1[e0 + tid] = s;
        }
    }
}

// ------------------------------------------------------------------
// Fully fused: h (+fp32 vector scatter) -> W_up -> W0+silu -> W1+silu
//              -> W2 + silu.w_out -> out1.  One 64-edge strip per CTA.
__global__ __launch_bounds__(256, 2)
void tower_fused(const float* __restrict__ x,  const float* __restrict__ rbf,
                 const int*   __restrict__ idx, const float* __restrict__ w_rbf,
                 const __half* __restrict__ wflat,
                 const float* __restrict__ bs, const float* __restrict__ wout,
                 float* __restrict__ xspe, float* __restrict__ out1)
{
    extern __shared__ __half smh[];
    const uint32_t sbt = smem_u32(smh);
    const uint32_t mbar0 = sbt + MBAR_OFF;
    const int tid = threadIdx.x;
    const size_t e0 = (size_t)blockIdx.x * 64;

    // init 2 pair-mbarriers; pre-issue pairs 0 and 1 (fills all 4 stages)
    if (tid == 0) {
        asm volatile("mbarrier.init.shared.b64 [%0], 1;" :: "r"(mbar0) : "memory");
        asm volatile("mbarrier.init.shared.b64 [%0], 1;" :: "r"(mbar0 + 8) : "memory");
    }
    __syncthreads();
    if (tid == 0) {
        issue_pair(sbt, wflat, 0);
        issue_pair(sbt, wflat, 1);
    }

    // h phase: row r = tid/4, cols (tid%4)*32 .. +31
    {
        const int r = tid >> 2;
        const int cg = (tid & 3) << 5;
        const float* xb = x + (e0 + r) * HH;
        const float* rb = rbf + (e0 + r) * RR;
        float r0 = __ldg(rb + 0), r1 = __ldg(rb + 1), r2 = __ldg(rb + 2);
        float r3 = __ldg(rb + 3), r4 = __ldg(rb + 4), r5 = __ldg(rb + 5);
        const int node = __ldg(idx + e0 + r);
        __half* trow = smh + r * TSTR2;
        float* xd = xspe + (size_t)node * HH;
#pragma unroll
        for (int cc = 0; cc < 32; cc += 4) {
            int c = cg + cc;
            float4 xv = __ldg((const float4*)(xb + c));
            float4 w0 = __ldg((const float4*)(w_rbf + 0 * HH + c));
            float4 w1 = __ldg((const float4*)(w_rbf + 1 * HH + c));
            float4 w2 = __ldg((const float4*)(w_rbf + 2 * HH + c));
            float4 w3 = __ldg((const float4*)(w_rbf + 3 * HH + c));
            float4 w4 = __ldg((const float4*)(w_rbf + 4 * HH + c));
            float4 w5 = __ldg((const float4*)(w_rbf + 5 * HH + c));
            float4 h;
            h.x = (r0*w0.x + r1*w1.x + r2*w2.x + r3*w3.x + r4*w4.x + r5*w5.x) * xv.x;
            h.y = (r0*w0.y + r1*w1.y + r2*w2.y + r3*w3.y + r4*w4.y + r5*w5.y) * xv.y;
            h.z = (r0*w0.z + r1*w1.z + r2*w2.z + r3*w3.z + r4*w4.z + r5*w5.z) * xv.z;
            h.w = (r0*w0.w + r1*w1.w + r2*w2.w + r3*w3.w + r4*w4.w + r5*w5.w) * xv.w;
            *reinterpret_cast<__half2*>(trow + c)     = __floats2half2_rn(h.x, h.y);
            *reinterpret_cast<__half2*>(trow + c + 2) = __floats2half2_rn(h.z, h.w);
            red_add_v4(xd + c, h.x, h.y, h.z, h.w);
        }
    }
    __syncthreads();

    // 4-layer tower; global pair bases: wup@0 (2), W0@2 (4), W1@6 (4), W2@10 (4)
    gemm_layer<2, false, false>(smh, sbt, 0,  wflat, nullptr, nullptr,
                                nullptr, e0);
    gemm_layer<4, true,  false>(smh, sbt, 2,  wflat, bs + 0 * DD, nullptr,
                                nullptr, e0);
    gemm_layer<4, true,  false>(smh, sbt, 6,  wflat, bs + 1 * DD, nullptr,
                                nullptr, e0);
    gemm_layer<4, true,  true >(smh, sbt, 10, wflat, bs + 2 * DD, wout,
                                out1, e0);
}

// ------------------------------------------------------------------
extern "C" void kernel_launch(void* const* d_in, const int* in_sizes, int n_in,
                              void* d_out, int out_size) {
    const float* x     = (const float*)d_in[0];
    const float* rbf   = (const float*)d_in[1];
    const int*   idx   = (const int*)  d_in[2];
    const float* w_rbf = (const float*)d_in[3];
    const float* w_up  = (const float*)d_in[4];
    const float* Ws    = (const float*)d_in[5];
    const float* bs    = (const float*)d_in[6];
    const float* w_out = (const float*)d_in[7];

    const int E = in_sizes[2];                    // 400000

    float* out_f = (float*)d_out;
    float* xspe  = out_f;                         // [N,128]
    float* out1  = out_f + (size_t)NN * HH;       // [E]

    __half* pwflat;
    cudaGetSymbolAddress((void**)&pwflat, g_wflat);

    cudaFuncSetAttribute(tower_fused,
                         cudaFuncAttributeMaxDynamicSharedMemorySize, SMEM_BYTES);

    // 0) build flat pre-swizzled fp16 weight image
    {
        int tot = NCHUNK_TOTAL * CH_FL;
        convert_weights<<<(tot + 255) / 256, 256>>>(w_up, Ws, pwflat);
    }
    // 1) zero x_spe (out1 fully written by the fused kernel)
    {
        int n4 = (NN * HH) / 4;
        zero_kernel<<<(n4 + 255) / 256, 256>>>((float4*)xspe, n4);
    }
    // 2) fully fused tower with pair-granular bulk weight stream
    {
        int grid = E / 64;                        // 6250
        tower_fused<<<grid, 256, SMEM_BYTES>>>(x, rbf, idx, w_rbf, pwflat,
                                               bs, w_out, xspe, out1);
    }
}

// round 17
// speedup vs baseline: 1.2060x; 1.0551x over previous
#include <cuda_runtime.h>
#include <cuda_fp16.h>
#include <math.h>
#include <stdint.h>

// Fixed problem shapes
#define EE 400000
#define NN 50000
#define RR 6
#define HH 128
#define DD 256

// Flat pre-swizzled fp16 weights: 28 chunks x 8192 halves (16KB).
// chunk g: rows n=0..255, k-cols k0..k0+31; within row, 8-half segment s
// stored at physical slot s ^ ((n>>1)&3).
#define NCHUNK_TOTAL 28      // wup:4  W0:8  W1:8  W2:8   (K32 chunks)
#define NPAIR_TOTAL 14
#define CH_FL 8192
__device__ __half g_wflat[(size_t)NCHUNK_TOTAL * CH_FL];

// SMEM (halves): t strip 64 x 264 | 4 weight stages of 8192 | 2 full mbars
#define TSTR2 264
#define T_FL2 16896
#define MBAR_OFF ((T_FL2 + 4 * CH_FL) * 2)        // 99328 bytes
#define SMEM_BYTES (MBAR_OFF + 32)                // 99360 -> 2 CTAs/SM

// ------------------------------------------------------------------
__device__ __forceinline__ uint32_t smem_u32(const void* p) {
    uint32_t a;
    asm("{ .reg .u64 t; cvta.to.shared.u64 t, %1; cvt.u32.u64 %0, t; }"
        : "=r"(a) : "l"(p));
    return a;
}
__device__ __forceinline__ void ldsm4(uint32_t& r0, uint32_t& r1,
                                      uint32_t& r2, uint32_t& r3,
                                      uint32_t addr) {
    asm volatile("ldmatrix.sync.aligned.m8n8.x4.shared.b16 {%0,%1,%2,%3}, [%4];"
                 : "=r"(r0), "=r"(r1), "=r"(r2), "=r"(r3) : "r"(addr));
}
__device__ __forceinline__ void mma_f16(float* c, const uint32_t* a,
                                        const uint32_t* b) {
    asm volatile(
        "mma.sync.aligned.m16n8k16.row.col.f32.f16.f16.f32 "
        "{%0,%1,%2,%3}, {%4,%5,%6,%7}, {%8,%9}, {%0,%1,%2,%3};"
        : "+f"(c[0]), "+f"(c[1]), "+f"(c[2]), "+f"(c[3])
        : "r"(a[0]), "r"(a[1]), "r"(a[2]), "r"(a[3]), "r"(b[0]), "r"(b[1]));
}
__device__ __forceinline__ float silu(float v) {
    return __fdividef(v, 1.f + __expf(-v));
}
__device__ __forceinline__ void red_add_v4(float* addr, float a, float b,
                                           float c, float d) {
    asm volatile("red.global.add.v4.f32 [%0], {%1, %2, %3, %4};"
                 :: "l"(addr), "f"(a), "f"(b), "f"(c), "f"(d) : "memory");
}
__device__ __forceinline__ void bulk_cp(uint32_t mbar, uint32_t dst,
                                        const __half* src) {
    asm volatile(
        "cp.async.bulk.shared::cta.global.mbarrier::complete_tx::bytes "
        "[%0], [%1], %2, [%3];"
        :: "r"(dst), "l"(src), "r"(16384u), "r"(mbar) : "memory");
}
// pair p: chunks 2p,2p+1 -> stages 2(p&1), 2(p&1)+1; full mbar per parity
__device__ __forceinline__ void issue_pair(uint32_t sbt,
                                           const __half* __restrict__ wflat,
                                           int p) {
    const uint32_t mbar = sbt + MBAR_OFF + (uint32_t)(p & 1) * 8;
    asm volatile("mbarrier.arrive.expect_tx.shared.b64 _, [%0], %1;"
                 :: "r"(mbar), "r"(32768u) : "memory");
    const int st0 = 2 * (p & 1);
    bulk_cp(mbar, sbt + (uint32_t)(T_FL2 + st0 * CH_FL) * 2,
            wflat + (size_t)(2 * p) * CH_FL);
    bulk_cp(mbar, sbt + (uint32_t)(T_FL2 + (st0 + 1) * CH_FL) * 2,
            wflat + (size_t)(2 * p + 1) * CH_FL);
}
__device__ __forceinline__ void mbar_wait(uint32_t mbar, uint32_t parity) {
    asm volatile(
        "{\n\t.reg .pred P;\n"
        "WAIT_%=:\n\t"
        "mbarrier.try_wait.parity.acquire.cta.shared::cta.b64 P, [%0], %1, 0x989680;\n\t"
        "@P bra.uni DONE_%=;\n\t"
        "bra.uni WAIT_%=;\n"
        "DONE_%=:\n\t}"
        :: "r"(mbar), "r"(parity) : "memory");
}
// named producer/consumer barriers (ids 1,2): consumers arrive (non-blocking),
// producer warp syncs (blocks until 224 consumer arrivals + its 32 threads)
__device__ __forceinline__ void nbar_arrive(int bid) {
    asm volatile("bar.arrive %0, %1;" :: "r"(bid), "r"(256) : "memory");
}
__device__ __forceinline__ void nbar_sync(int bid) {
    asm volatile("bar.sync %0, %1;" :: "r"(bid), "r"(256) : "memory");
}

// ------------------------------------------------------------------
__global__ void zero_kernel(float4* p, int n4) {
    int i = blockIdx.x * blockDim.x + threadIdx.x;
    if (i < n4) p[i] = make_float4(0.f, 0.f, 0.f, 0.f);
}

// Build flat pre-swizzled fp16 weight image.
__global__ void convert_weights(const float* __restrict__ wup,
                                const float* __restrict__ Ws,
                                __half* __restrict__ wflat) {
    int i = blockIdx.x * blockDim.x + threadIdx.x;
    if (i >= NCHUNK_TOTAL * CH_FL) return;
    int g = i >> 13;
    int r = i & (CH_FL - 1);
    int n = r >> 5;
    int rest = r & 31;
    int sp = rest >> 3, j = rest & 7;
    int slog = sp ^ ((n >> 1) & 3);       // logical k-segment
    int kl = slog * 8 + j;                // k within chunk
    float v;
    if (g < 4) {
        v = wup[(g * 32 + kl) * DD + n];
    } else {
        int gg = g - 4;
        int l = gg >> 3, k0 = (gg & 7) * 32;
        v = Ws[(size_t)l * DD * DD + (size_t)(k0 + kl) * DD + n];
    }
    wflat[i] = __float2half(v);
}

// ------------------------------------------------------------------
// One fp16 layer; weights arrive as chunk-PAIRS. Full side: TMA mbarrier
// (proven R12-R15). Empty side: named barriers — warps 1..7 bar.arrive
// after consuming a pair; warp 0 bar.syncs before recycling that slot.
// Consumers never block on stage reuse.
template<int NP, bool ACT, bool LAST>
__device__ __forceinline__ void gemm_layer(
    __half* smh, uint32_t sbt, int pbase, const __half* __restrict__ wflat,
    const float* __restrict__ bias, const float* __restrict__ wout,
    float* __restrict__ out1, size_t e0)
{
    const int tid = threadIdx.x;
    const int wn = tid >> 5, lane = tid & 31;
    const int g2 = lane >> 2, t = lane & 3;
    const uint32_t full0 = sbt + MBAR_OFF;

    const uint32_t a_base = sbt +
        (uint32_t)((lane & 15) * TSTR2 + ((lane & 16) ? 8 : 0)) * 2;

    const int sb_ = (lane & 8) ? 1 : 0;
    uint32_t rowoff[2];
    int sw[2];
#pragma unroll
    for (int np = 0; np < 2; np++) {
        int row = wn * 32 + np * 16 + (lane & 7) + ((lane & 16) ? 8 : 0);
        rowoff[np] = (uint32_t)row * 64u;
        sw[np] = (row >> 1) & 3;
    }

    float acc[4][4][4];
#pragma unroll
    for (int i = 0; i < 4; i++)
#pragma unroll
        for (int j = 0; j < 4; j++)
#pragma unroll
            for (int q = 0; q < 4; q++) acc[i][j][q] = 0.f;

#pragma unroll 1
    for (int lp = 0; lp < NP; lp++) {
        const int p = pbase + lp;
        // producer (warp 0): wait until slot (p+1)&1's previous pair (p-1)
        // is consumed by warps 1..7 (own consumption is program-ordered),
        // then recycle the slot with pair p+1.
        const int pn = p + 1;
        if (wn == 0 && pn >= 2 && pn < NPAIR_TOTAL) {
            nbar_sync(1 + (pn & 1));
            if (lane == 0) issue_pair(sbt, wflat, pn);
        }
        mbar_wait(full0 + (uint32_t)(p & 1) * 8, (uint32_t)((p >> 1) & 1));

        const int st0 = 2 * (p & 1);
#pragma unroll
        for (int hh = 0; hh < 2; hh++) {
            const uint32_t stg = sbt + (uint32_t)(T_FL2 + (st0 + hh) * CH_FL) * 2;
#pragma unroll
            for (int ks = 0; ks < 2; ks++) {
                uint32_t af[4][4], bf[4][2];
                const uint32_t ak =
                    (uint32_t)((2 * lp + hh) * 32 + ks * 16) * 2;
#pragma unroll
                for (int mf = 0; mf < 4; mf++)
                    ldsm4(af[mf][0], af[mf][1], af[mf][2], af[mf][3],
                          a_base + ak + (uint32_t)(mf * 16 * TSTR2) * 2);
#pragma unroll
                for (int np = 0; np < 2; np++) {
                    uint32_t d0, d1, d2, d3;
                    uint32_t addr = stg + rowoff[np] +
                                    (uint32_t)(((2 * ks + sb_) ^ sw[np]) << 4);
                    ldsm4(d0, d1, d2, d3, addr);
                    bf[2 * np][0] = d0;     bf[2 * np][1] = d1;
                    bf[2 * np + 1][0] = d2; bf[2 * np + 1][1] = d3;
                }
#pragma unroll
                for (int mf = 0; mf < 4; mf++)
#pragma unroll
                    for (int nf = 0; nf < 4; nf++)
                        mma_f16(acc[mf][nf], af[mf], bf[nf]);
            }
        }
        // consumers signal pair consumption (non-blocking)
        if (wn != 0) nbar_arrive(1 + (p & 1));
    }

    if (!LAST) {
        __syncthreads();   // all warps' MMAs done before t strip is rewritten
#pragma unroll
        for (int mf = 0; mf < 4; mf++) {
#pragma unroll
            for (int nf = 0; nf < 4; nf++) {
                int r0 = mf * 16 + g2;
                int cc = wn * 32 + nf * 8 + 2 * t;
                float v0 = acc[mf][nf][0], v1 = acc[mf][nf][1];
                float v2 = acc[mf][nf][2], v3 = acc[mf][nf][3];
                if (ACT) {
                    float b0 = __ldg(bias + cc), b1 = __ldg(bias + cc + 1);
                    v0 = silu(v0 + b0); v1 = silu(v1 + b1);
                    v2 = silu(v2 + b0); v3 = silu(v3 + b1);
                }
                *reinterpret_cast<__half2*>(smh + r0 * TSTR2 + cc) =
                    __floats2half2_rn(v0, v1);
                *reinterpret_cast<__half2*>(smh + (r0 + 8) * TSTR2 + cc) =
                    __floats2half2_rn(v2, v3);
            }
        }
        __syncthreads();
    } else {
        float s0[4], s1[4];
#pragma unroll
        for (int mf = 0; mf < 4; mf++) { s0[mf] = 0.f; s1[mf] = 0.f; }
#pragma unroll
        for (int mf = 0; mf < 4; mf++) {
#pragma unroll
            for (int nf = 0; nf < 4; nf++) {
                int cc = wn * 32 + nf * 8 + 2 * t;
                float b0 = __ldg(bias + cc), b1 = __ldg(bias + cc + 1);
                float w0 = __ldg(wout + cc), w1 = __ldg(wout + cc + 1);
                s0[mf] += silu(acc[mf][nf][0] + b0) * w0
                        + silu(acc[mf][nf][1] + b1) * w1;
                s1[mf] += silu(acc[mf][nf][2] + b0) * w0
                        + silu(acc[mf][nf][3] + b1) * w1;
            }
        }
#pragma unroll
        for (int mf = 0; mf < 4; mf++) {
            s0[mf] += __shfl_xor_sync(0xffffffffu, s0[mf], 1);
            s0[mf] += __shfl_xor_sync(0xffffffffu, s0[mf], 2);
            s1[mf] += __shfl_xor_sync(0xffffffffu, s1[mf], 1);
            s1[mf] += __shfl_xor_sync(0xffffffffu, s1[mf], 2);
        }
        __syncthreads();   // all warps past the loop; stages now reusable
        float* red = reinterpret_cast<float*>(smh + T_FL2);
        if (t == 0) {
#pragma unroll
            for (int mf = 0; mf < 4; mf++) {
                red[(mf * 16 + g2) * 8 + wn] = s0[mf];
                red[(mf * 16 + 8 + g2) * 8 + wn] = s1[mf];
            }
        }
        __syncthreads();
        if (tid < 64) {
            float s = 0.f;
#pragma unroll
            for (int j = 0; j < 8; j++) s += red[tid * 8 + j];
            out1[e0 + tid] = s;
        }
    }
}

// ------------------------------------------------------------------
// Fully fused: h (+fp32 vector scatter) -> W_up -> W0+silu -> W1+silu
//              -> W2 + silu.w_out -> out1.  One 64-edge strip per CTA.
__global__ __launch_bounds__(256, 2)
void tower_fused(const float* __restrict__ x,  const float* __restrict__ rbf,
                 const int*   __restrict__ idx, const float* __restrict__ w_rbf,
                 const __half* __restrict__ wflat,
                 const float* __restrict__ bs, const float* __restrict__ wout,
                 float* __restrict__ xspe, float* __restrict__ out1)
{
    extern __shared__ __half smh[];
    const uint32_t sbt = smem_u32(smh);
    const uint32_t mbar0 = sbt + MBAR_OFF;
    const int tid = threadIdx.x;
    const size_t e0 = (size_t)blockIdx.x * 64;

    // init 2 pair-full mbarriers; pre-issue pairs 0 and 1 (all 4 stages)
    if (tid == 0) {
        asm volatile("mbarrier.init.shared.b64 [%0], 1;" :: "r"(mbar0) : "memory");
        asm volatile("mbarrier.init.shared.b64 [%0], 1;" :: "r"(mbar0 + 8) : "memory");
    }
    __syncthreads();
    if (tid == 0) {
        issue_pair(sbt, wflat, 0);
        issue_pair(sbt, wflat, 1);
    }

    // h phase: row r = tid/4, cols (tid%4)*32 .. +31
    {
        const int r = tid >> 2;
        const int cg = (tid & 3) << 5;
        const float* xb = x + (e0 + r) * HH;
        const float* rb = rbf + (e0 + r) * RR;
        float r0 = __ldg(rb + 0), r1 = __ldg(rb + 1), r2 = __ldg(rb + 2);
        float r3 = __ldg(rb + 3), r4 = __ldg(rb + 4), r5 = __ldg(rb + 5);
        const int node = __ldg(idx + e0 + r);
        __half* trow = smh + r * TSTR2;
        float* xd = xspe + (size_t)node * HH;
#pragma unroll
        for (int cc = 0; cc < 32; cc += 4) {
            int c = cg + cc;
            float4 xv = __ldg((const float4*)(xb + c));
            float4 w0 = __ldg((const float4*)(w_rbf + 0 * HH + c));
            float4 w1 = __ldg((const float4*)(w_rbf + 1 * HH + c));
            float4 w2 = __ldg((const float4*)(w_rbf + 2 * HH + c));
            float4 w3 = __ldg((const float4*)(w_rbf + 3 * HH + c));
            float4 w4 = __ldg((const float4*)(w_rbf + 4 * HH + c));
            float4 w5 = __ldg((const float4*)(w_rbf + 5 * HH + c));
            float4 h;
            h.x = (r0*w0.x + r1*w1.x + r2*w2.x + r3*w3.x + r4*w4.x + r5*w5.x) * xv.x;
            h.y = (r0*w0.y + r1*w1.y + r2*w2.y + r3*w3.y + r4*w4.y + r5*w5.y) * xv.y;
            h.z = (r0*w0.z + r1*w1.z + r2*w2.z + r3*w3.z + r4*w4.z + r5*w5.z) * xv.z;
            h.w = (r0*w0.w + r1*w1.w + r2*w2.w + r3*w3.w + r4*w4.w + r5*w5.w) * xv.w;
            *reinterpret_cast<__half2*>(trow + c)     = __floats2half2_rn(h.x, h.y);
            *reinterpret_cast<__half2*>(trow + c + 2) = __floats2half2_rn(h.z, h.w);
            red_add_v4(xd + c, h.x, h.y, h.z, h.w);
        }
    }
    __syncthreads();

    // 4-layer tower; global pair bases: wup@0 (2), W0@2 (4), W1@6 (4), W2@10 (4)
    gemm_layer<2, false, false>(smh, sbt, 0,  wflat, nullptr, nullptr,
                                nullptr, e0);
    gemm_layer<4, true,  false>(smh, sbt, 2,  wflat, bs + 0 * DD, nullptr,
                                nullptr, e0);
    gemm_layer<4, true,  false>(smh, sbt, 6,  wflat, bs + 1 * DD, nullptr,
                                nullptr, e0);
    gemm_layer<4, true,  true >(smh, sbt, 10, wflat, bs + 2 * DD, wout,
                                out1, e0);
}

// ------------------------------------------------------------------
extern "C" void kernel_launch(void* const* d_in, const int* in_sizes, int n_in,
                              void* d_out, int out_size) {
    const float* x     = (const float*)d_in[0];
    const float* rbf   = (const float*)d_in[1];
    const int*   idx   = (const int*)  d_in[2];
    const float* w_rbf = (const float*)d_in[3];
    const float* w_up  = (const float*)d_in[4];
    const float* Ws    = (const float*)d_in[5];
    const float* bs    = (const float*)d_in[6];
    const float* w_out = (const float*)d_in[7];

    const int E = in_sizes[2];                    // 400000

    float* out_f = (float*)d_out;
    float* xspe  = out_f;                         // [N,128]
    float* out1  = out_f + (size_t)NN * HH;       // [E]

    __half* pwflat;
    cudaGetSymbolAddress((void**)&pwflat, g_wflat);

    cudaFuncSetAttribute(tower_fused,
                         cudaFuncAttributeMaxDynamicSharedMemorySize, SMEM_BYTES);

    // 0) build flat pre-swizzled fp16 weight image
    {
        int tot = NCHUNK_TOTAL * CH_FL;
        convert_weights<<<(tot + 255) / 256, 256>>>(w_up, Ws, pwflat);
    }
    // 1) zero x_spe (out1 fully written by the fused kernel)
    {
        int n4 = (NN * HH) / 4;
        zero_kernel<<<(n4 + 255) / 256, 256>>>((float4*)xspe, n4);
    }
    // 2) fully fused tower, named-barrier decoupled weight stream
    {
        int grid = E / 64;                        // 6250
        tower_fused<<<grid, 256, SMEM_BYTES>>>(x, rbf, idx, w_rbf, pwflat,
                                               bs, w_out, xspe, out1);
    }
}